// round 7
// baseline (speedup 1.0000x reference)
#include <cuda_runtime.h>
#include <cuda_bf16.h>

#define N_NODES 100000
#define N_EDGES 1600000
#define D 128
#define KTOT 256
#define IRS 260
#define TILE_R 64
#define GEMM_THREADS 256
#define SMEM_BYTES (KTOT*D*4 + TILE_R*IRS*4 + D*4)   // 198144

#define SCAN_CHUNK 256
#define NBLK_SCAN ((N_NODES + SCAN_CHUNK - 1) / SCAN_CHUNK)   // 391

// ---------------- device scratch ----------------
__device__ __align__(16) float g_agg[(size_t)N_NODES * D];
__device__ __align__(16) float g_h1[(size_t)N_NODES * D];
__device__ __align__(16) float g_wcat1[KTOT * D];
__device__ __align__(16) float g_wcat2[KTOT * D];
__device__ __align__(16) int   g_degi[N_NODES];
__device__ __align__(16) int   g_rowstart[N_NODES];
__device__ __align__(16) int   g_cursor[N_NODES];
__device__ __align__(16) int   g_col[N_EDGES];
__device__ __align__(16) int   g_bsum[NBLK_SCAN];
__device__ __align__(16) int   g_boff[NBLK_SCAN];

// ---------------- f32x2 helpers ----------------
__device__ __forceinline__ unsigned long long ffma2(unsigned long long a,
                                                    unsigned long long b,
                                                    unsigned long long c) {
    unsigned long long d;
    asm("fma.rn.f32x2 %0, %1, %2, %3;" : "=l"(d) : "l"(a), "l"(b), "l"(c));
    return d;
}
__device__ __forceinline__ unsigned long long pack2(float x) {
    unsigned long long d;
    asm("mov.b64 %0, {%1, %1};" : "=l"(d) : "f"(x));
    return d;
}
__device__ __forceinline__ float2 unpack2(unsigned long long v) {
    float2 r;
    asm("mov.b64 {%0, %1}, %2;" : "=f"(r.x), "=f"(r.y) : "l"(v));
    return r;
}

// ---------------- utility ----------------
__global__ void zero4_kernel(float4* __restrict__ p, int n4) {
    int i = blockIdx.x * blockDim.x + threadIdx.x;
    if (i < n4) p[i] = make_float4(0.f, 0.f, 0.f, 0.f);
}
__global__ void zeroi_kernel(int* __restrict__ p, int n) {
    int i = blockIdx.x * blockDim.x + threadIdx.x;
    if (i < n) p[i] = 0;
}
__global__ void degi_kernel(const int* __restrict__ dst, int* __restrict__ deg) {
    int e = blockIdx.x * blockDim.x + threadIdx.x;
    if (e < N_EDGES) atomicAdd(&deg[dst[e]], 1);
}

// ---------------- scan (3-phase parallel) ----------------
__global__ void blocksum_kernel(const int* __restrict__ deg, int* __restrict__ bsum) {
    __shared__ int warp_s[8];
    int b = blockIdx.x;
    int i = b * SCAN_CHUNK + threadIdx.x;
    int v = (i < N_NODES) ? deg[i] : 0;
#pragma unroll
    for (int m = 16; m >= 1; m >>= 1) v += __shfl_xor_sync(0xffffffffu, v, m);
    if ((threadIdx.x & 31) == 0) warp_s[threadIdx.x >> 5] = v;
    __syncthreads();
    if (threadIdx.x == 0) {
        int s = 0;
#pragma unroll
        for (int w = 0; w < 8; w++) s += warp_s[w];
        bsum[b] = s;
    }
}
__global__ void scanbsum_kernel(const int* __restrict__ bsum, int* __restrict__ boff) {
    __shared__ int s[512];
    int t = threadIdx.x;
    s[t] = (t < NBLK_SCAN) ? bsum[t] : 0;
    __syncthreads();
    for (int off = 1; off < 512; off <<= 1) {
        int v = (t >= off) ? s[t - off] : 0;
        __syncthreads();
        s[t] += v;
        __syncthreads();
    }
    if (t < NBLK_SCAN) boff[t] = (t == 0) ? 0 : s[t - 1];
}
__global__ void scanfinal_kernel(const int* __restrict__ deg, const int* __restrict__ boff,
                                 int* __restrict__ rowstart, int* __restrict__ cursor) {
    __shared__ int warp_s[8];
    int b = blockIdx.x;
    int t = threadIdx.x;
    int lane = t & 31, w = t >> 5;
    int i = b * SCAN_CHUNK + t;
    int v = (i < N_NODES) ? deg[i] : 0;
    int sc = v;
#pragma unroll
    for (int m = 1; m < 32; m <<= 1) {
        int u = __shfl_up_sync(0xffffffffu, sc, m);
        if (lane >= m) sc += u;
    }
    if (lane == 31) warp_s[w] = sc;
    __syncthreads();
    int wbase = 0;
#pragma unroll
    for (int q = 0; q < 8; q++) wbase += (q < w) ? warp_s[q] : 0;
    int excl = boff[b] + wbase + sc - v;
    if (i < N_NODES) { rowstart[i] = excl; cursor[i] = excl; }
}
__global__ void fill_kernel(const int* __restrict__ src, const int* __restrict__ dst,
                            int* __restrict__ cursor, int* __restrict__ col) {
    int e = blockIdx.x * blockDim.x + threadIdx.x;
    if (e < N_EDGES) {
        int d = dst[e];
        int p = atomicAdd(&cursor[d], 1);
        col[p] = src[e];
    }
}

// ---------------- edge-balanced gather: 32 CSR slots per warp ----------------
// Accumulates contiguous runs (CSR sorted by dst) and flushes per-node partial
// sums with float4 atomics into zeroed agg. Mean division happens in GEMM
// staging. Node-boundary logic is warp-uniform (no divergence).
__global__ void gatherE_kernel(const float* __restrict__ feat,
                               const int* __restrict__ rowstart,
                               const int* __restrict__ col,
                               float* __restrict__ agg) {
    const int warp = (blockIdx.x * blockDim.x + threadIdx.x) >> 5;
    const int lane = threadIdx.x & 31;
    const int p0 = warp * 32;
    if (p0 >= N_EDGES) return;
    const int cnt = min(32, N_EDGES - p0);
    const int c4 = lane << 2;

    // each lane holds one col value; distributed via shfl
    int myc = (lane < cnt) ? __ldg(&col[p0 + lane]) : 0;

    // binary search: largest node with rowstart[node] <= p0
    int lo = 0, hi = N_NODES - 1;
    while (lo < hi) {
        int mid = (lo + hi + 1) >> 1;
        if (__ldg(&rowstart[mid]) <= p0) lo = mid; else hi = mid - 1;
    }
    int node = lo;
    int nend = (node + 1 < N_NODES) ? __ldg(&rowstart[node + 1]) : N_EDGES;

    float4 acc = make_float4(0.f, 0.f, 0.f, 0.f);
    bool dirty = false;

    int e = 0;
    while (e < cnt) {
        const int batch = min(8, cnt - e);
        float4 v[8];
#pragma unroll
        for (int u = 0; u < 8; u++) {
            if (u < batch) {
                int s = __shfl_sync(0xffffffffu, myc, e + u);
                v[u] = *(const float4*)(feat + (size_t)s * D + c4);
            }
        }
#pragma unroll
        for (int u = 0; u < 8; u++) {
            if (u < batch) {
                acc.x += v[u].x; acc.y += v[u].y; acc.z += v[u].z; acc.w += v[u].w;
                dirty = true;
                int gpos = p0 + e + u + 1;           // next global position
                while (gpos == nend && node < N_NODES) {  // node complete
                    atomicAdd((float4*)(agg + (size_t)node * D + c4), acc);
                    acc = make_float4(0.f, 0.f, 0.f, 0.f);
                    dirty = false;
                    node++;
                    if (node >= N_NODES) break;      // all nodes done
                    nend = (node + 1 < N_NODES) ? __ldg(&rowstart[node + 1]) : N_EDGES;
                }
            }
        }
        e += batch;
    }
    if (dirty && node < N_NODES)
        atomicAdd((float4*)(agg + (size_t)node * D + c4), acc);
}

// ---------------- weight transpose/concat ----------------
__global__ void wcat_kernel(const float* __restrict__ Ws, const float* __restrict__ Wn,
                            float* __restrict__ wcat) {
    int idx = blockIdx.x * blockDim.x + threadIdx.x;
    if (idx >= D * KTOT) return;
    int j = idx >> 8;
    int k = idx & 255;
    float v = (k < D) ? Ws[j * D + k] : Wn[j * D + (k - D)];
    wcat[k * D + j] = v;
}

// ---------------- fused SAGE GEMM: 256 thr, 4 rows x 8 cols / thread --------
__global__ void __launch_bounds__(GEMM_THREADS, 1)
sage_gemm_kernel(const float* __restrict__ feat,
                 const float* __restrict__ wcat,
                 const float* __restrict__ bias,
                 const float* __restrict__ agg,      // raw sums; divide by deg here
                 const int* __restrict__ degi,
                 float* __restrict__ out,
                 int do_norm) {
    extern __shared__ float smem[];
    float* sw   = smem;                  // [256][128]
    float* sinp = smem + KTOT * D;       // [64][IRS]
    float* sb   = sinp + TILE_R * IRS;   // [128]

    const int tid = threadIdx.x;

    {
        const float4* wsrc = (const float4*)wcat;
        float4* wdst = (float4*)sw;
#pragma unroll 4
        for (int i = tid; i < (KTOT * D) / 4; i += GEMM_THREADS) wdst[i] = wsrc[i];
    }
    if (tid < D) sb[tid] = bias[tid];
    __syncthreads();

    const int ct = tid & 15;      // 16 col groups x 8 cols
    const int rt = tid >> 4;      // 16 row groups x 4 rows
    const int j0 = ct * 8;
    const int r0 = rt * 4;
    const int NT = (N_NODES + TILE_R - 1) / TILE_R;

    for (int tile = blockIdx.x; tile < NT; tile += gridDim.x) {
        const int row0 = tile * TILE_R;

        // stage [feat | agg/deg] tile
#pragma unroll 4
        for (int idx = tid; idx < TILE_R * (KTOT / 4); idx += GEMM_THREADS) {
            int r = idx >> 6;
            int q = idx & 63;
            int grow = row0 + r;
            float4 v = make_float4(0.f, 0.f, 0.f, 0.f);
            if (grow < N_NODES) {
                if (q < 32) {
                    v = *(const float4*)(feat + (size_t)grow * D + (q << 2));
                } else {
                    float inv = 1.0f / fmaxf((float)degi[grow], 1.0f);
                    v = __ldcs((const float4*)(agg + (size_t)grow * D + ((q - 32) << 2)));
                    v.x *= inv; v.y *= inv; v.z *= inv; v.w *= inv;
                }
            }
            *(float4*)(sinp + r * IRS + (q << 2)) = v;
        }
        __syncthreads();

        unsigned long long acc[16];
#pragma unroll
        for (int i = 0; i < 16; i++) acc[i] = 0ull;

        const float* a0 = sinp + r0 * IRS;
        for (int k = 0; k < KTOT; k += 2) {
            float2 a2[4];
#pragma unroll
            for (int r = 0; r < 4; r++)
                a2[r] = *(const float2*)(a0 + r * IRS + k);

            const float* wk0 = sw + (k << 7) + j0;
            ulonglong2 wA0 = *(const ulonglong2*)(wk0);
            ulonglong2 wB0 = *(const ulonglong2*)(wk0 + 4);
            const float* wk1 = wk0 + D;
            ulonglong2 wA1 = *(const ulonglong2*)(wk1);
            ulonglong2 wB1 = *(const ulonglong2*)(wk1 + 4);
#pragma unroll
            for (int r = 0; r < 4; r++) {
                unsigned long long av0 = pack2(a2[r].x);
                acc[r * 4 + 0] = ffma2(av0, wA0.x, acc[r * 4 + 0]);
                acc[r * 4 + 1] = ffma2(av0, wA0.y, acc[r * 4 + 1]);
                acc[r * 4 + 2] = ffma2(av0, wB0.x, acc[r * 4 + 2]);
                acc[r * 4 + 3] = ffma2(av0, wB0.y, acc[r * 4 + 3]);
            }
#pragma unroll
            for (int r = 0; r < 4; r++) {
                unsigned long long av1 = pack2(a2[r].y);
                acc[r * 4 + 0] = ffma2(av1, wA1.x, acc[r * 4 + 0]);
                acc[r * 4 + 1] = ffma2(av1, wA1.y, acc[r * 4 + 1]);
                acc[r * 4 + 2] = ffma2(av1, wB1.x, acc[r * 4 + 2]);
                acc[r * 4 + 3] = ffma2(av1, wB1.y, acc[r * 4 + 3]);
            }
        }

#pragma unroll
        for (int r = 0; r < 4; ++r) {
            float v[8];
            float2 t;
            t = unpack2(acc[r * 4 + 0]); v[0] = t.x; v[1] = t.y;
            t = unpack2(acc[r * 4 + 1]); v[2] = t.x; v[3] = t.y;
            t = unpack2(acc[r * 4 + 2]); v[4] = t.x; v[5] = t.y;
            t = unpack2(acc[r * 4 + 3]); v[6] = t.x; v[7] = t.y;
#pragma unroll
            for (int c = 0; c < 8; c++) v[c] += sb[j0 + c];

            float scale = 1.0f;
            if (do_norm) {
                float ss = 0.f;
#pragma unroll
                for (int c = 0; c < 8; c++) ss += v[c] * v[c];
#pragma unroll
                for (int m = 8; m >= 1; m >>= 1)
                    ss += __shfl_xor_sync(0xffffffffu, ss, m);
                scale = 1.0f / fmaxf(sqrtf(ss), 1e-12f);
            }

            int grow = row0 + r0 + r;
            if (grow < N_NODES) {
                float* op = out + (size_t)grow * D + j0;
                float4 o;
                o.x = v[0] * scale; o.y = v[1] * scale;
                o.z = v[2] * scale; o.w = v[3] * scale;
                if (do_norm) __stcs((float4*)op, o); else *(float4*)op = o;
                o.x = v[4] * scale; o.y = v[5] * scale;
                o.z = v[6] * scale; o.w = v[7] * scale;
                if (do_norm) __stcs((float4*)(op + 4), o); else *(float4*)(op + 4) = o;
            }
        }
        __syncthreads();
    }
}

// ---------------- launch ----------------
extern "C" void kernel_launch(void* const* d_in, const int* in_sizes, int n_in,
                              void* d_out, int out_size) {
    const float* x   = (const float*)d_in[0];
    const int* src   = (const int*)d_in[1];
    const int* dst   = (const int*)d_in[2];
    const float* Ws1 = (const float*)d_in[3];
    const float* Wn1 = (const float*)d_in[4];
    const float* b1  = (const float*)d_in[5];
    const float* Ws2 = (const float*)d_in[6];
    const float* Wn2 = (const float*)d_in[7];
    const float* b2  = (const float*)d_in[8];
    float* out = (float*)d_out;

    float* agg;   cudaGetSymbolAddress((void**)&agg, g_agg);
    float* h1;    cudaGetSymbolAddress((void**)&h1, g_h1);
    float* wcat1; cudaGetSymbolAddress((void**)&wcat1, g_wcat1);
    float* wcat2; cudaGetSymbolAddress((void**)&wcat2, g_wcat2);
    int* degi;    cudaGetSymbolAddress((void**)&degi, g_degi);
    int* rowst;   cudaGetSymbolAddress((void**)&rowst, g_rowstart);
    int* cursor;  cudaGetSymbolAddress((void**)&cursor, g_cursor);
    int* col;     cudaGetSymbolAddress((void**)&col, g_col);
    int* bsum;    cudaGetSymbolAddress((void**)&bsum, g_bsum);
    int* boff;    cudaGetSymbolAddress((void**)&boff, g_boff);

    int sms = 148;
    cudaDeviceGetAttribute(&sms, cudaDevAttrMultiProcessorCount, 0);
    cudaFuncSetAttribute(sage_gemm_kernel,
                         cudaFuncAttributeMaxDynamicSharedMemorySize, SMEM_BYTES);

    // ---- CSR build ----
    zeroi_kernel<<<(N_NODES + 255) / 256, 256>>>(degi, N_NODES);
    degi_kernel<<<(N_EDGES + 255) / 256, 256>>>(dst, degi);
    blocksum_kernel<<<NBLK_SCAN, SCAN_CHUNK>>>(degi, bsum);
    scanbsum_kernel<<<1, 512>>>(bsum, boff);
    scanfinal_kernel<<<NBLK_SCAN, SCAN_CHUNK>>>(degi, boff, rowst, cursor);
    fill_kernel<<<(N_EDGES + 255) / 256, 256>>>(src, dst, cursor, col);

    // ---- weight transposes ----
    wcat_kernel<<<(KTOT * D + 255) / 256, 256>>>(Ws1, Wn1, wcat1);
    wcat_kernel<<<(KTOT * D + 255) / 256, 256>>>(Ws2, Wn2, wcat2);

    const int NAGG4 = N_NODES * D / 4;
    const int GB = ((N_EDGES + 31) / 32 + 7) / 8;   // 8 warps/block, 32 edges/warp

    // ---- layer 1 ----
    zero4_kernel<<<(NAGG4 + 255) / 256, 256>>>((float4*)agg, NAGG4);
    gatherE_kernel<<<GB, 256>>>(x, rowst, col, agg);
    sage_gemm_kernel<<<sms, GEMM_THREADS, SMEM_BYTES>>>(x, wcat1, b1, agg, degi, h1, 0);

    // ---- layer 2 ----
    zero4_kernel<<<(NAGG4 + 255) / 256, 256>>>((float4*)agg, NAGG4);
    gatherE_kernel<<<GB, 256>>>(h1, rowst, col, agg);
    sage_gemm_kernel<<<sms, GEMM_THREADS, SMEM_BYTES>>>(h1, wcat2, b2, agg, degi, out, 1);
}

// round 8
// speedup vs baseline: 1.0843x; 1.0843x over previous
#include <cuda_runtime.h>
#include <cuda_fp16.h>

#define N_NODES 100000
#define N_EDGES 1600000
#define D 128
#define KTOT 256
#define IRS 260
#define TILE_R 64
#define GEMM_THREADS 128
#define SMEM_BYTES (KTOT*D*4 + TILE_R*IRS*4 + D*4)   // 198144

// ---------------- device scratch ----------------
__device__ __align__(16) float  g_agg[(size_t)N_NODES * D];
__device__ __align__(16) float  g_h1[(size_t)N_NODES * D];
__device__ __align__(16) __half g_f16[(size_t)N_NODES * D];   // fp16 shadow of layer input
__device__ __align__(16) float  g_wcat1[KTOT * D];
__device__ __align__(16) float  g_wcat2[KTOT * D];
__device__ __align__(16) int    g_degi[N_NODES];
__device__ __align__(16) int    g_rowstart[N_NODES];
__device__ __align__(16) int    g_cursor[N_NODES];
__device__ __align__(16) int    g_col[N_EDGES];

// ---------------- f32x2 helpers ----------------
__device__ __forceinline__ unsigned long long ffma2(unsigned long long a,
                                                    unsigned long long b,
                                                    unsigned long long c) {
    unsigned long long d;
    asm("fma.rn.f32x2 %0, %1, %2, %3;" : "=l"(d) : "l"(a), "l"(b), "l"(c));
    return d;
}
__device__ __forceinline__ unsigned long long pack2(float x) {
    unsigned long long d;
    asm("mov.b64 %0, {%1, %1};" : "=l"(d) : "f"(x));
    return d;
}
__device__ __forceinline__ float2 unpack2(unsigned long long v) {
    float2 r;
    asm("mov.b64 {%0, %1}, %2;" : "=f"(r.x), "=f"(r.y) : "l"(v));
    return r;
}

// ---------------- fused degree histogram + x -> fp16 conversion ----------------
__global__ void degx2h_kernel(const int* __restrict__ dst, int* __restrict__ degi,
                              const float* __restrict__ x, __half* __restrict__ x16) {
    int i = blockIdx.x * blockDim.x + threadIdx.x;
    if (i < N_EDGES) atomicAdd(&degi[dst[i]], 1);
    if (i < N_NODES * D / 4) {
        float4 v = *(const float4*)(x + (size_t)i * 4);
        __half2 a = __floats2half2_rn(v.x, v.y);
        __half2 b = __floats2half2_rn(v.z, v.w);
        uint2 u = make_uint2(*(unsigned*)&a, *(unsigned*)&b);
        *(uint2*)(x16 + (size_t)i * 4) = u;
    }
}

// ---------------- single-block pass-based exclusive scan (int4, 25 passes) ----
__global__ void scan_kernel(const int* __restrict__ deg,
                            int* __restrict__ rowstart, int* __restrict__ cursor) {
    __shared__ int wsums[32];
    __shared__ int running_s;
    const int t = threadIdx.x;
    const int lane = t & 31, w = t >> 5;
    if (t == 0) running_s = 0;
    __syncthreads();

    for (int base = 0; base < N_NODES; base += 4096) {
        int i0 = base + t * 4;
        int4 d4 = make_int4(0, 0, 0, 0);
        if (i0 + 3 < N_NODES) d4 = *(const int4*)(deg + i0);
        else {
            if (i0 + 0 < N_NODES) d4.x = deg[i0 + 0];
            if (i0 + 1 < N_NODES) d4.y = deg[i0 + 1];
            if (i0 + 2 < N_NODES) d4.z = deg[i0 + 2];
        }
        int tsum = d4.x + d4.y + d4.z + d4.w;
        int sc = tsum;
#pragma unroll
        for (int m = 1; m < 32; m <<= 1) {
            int u = __shfl_up_sync(0xffffffffu, sc, m);
            if (lane >= m) sc += u;
        }
        if (lane == 31) wsums[w] = sc;
        __syncthreads();
        if (w == 0) {
            int ws = wsums[lane];
            int s2 = ws;
#pragma unroll
            for (int m = 1; m < 32; m <<= 1) {
                int u = __shfl_up_sync(0xffffffffu, s2, m);
                if (lane >= m) s2 += u;
            }
            wsums[lane] = s2;
        }
        __syncthreads();
        int excl = running_s + (w > 0 ? wsums[w - 1] : 0) + sc - tsum;
        int r = excl;
        if (i0 + 0 < N_NODES) { rowstart[i0 + 0] = r; cursor[i0 + 0] = r; } r += d4.x;
        if (i0 + 1 < N_NODES) { rowstart[i0 + 1] = r; cursor[i0 + 1] = r; } r += d4.y;
        if (i0 + 2 < N_NODES) { rowstart[i0 + 2] = r; cursor[i0 + 2] = r; } r += d4.z;
        if (i0 + 3 < N_NODES) { rowstart[i0 + 3] = r; cursor[i0 + 3] = r; }
        int total = wsums[31];
        __syncthreads();
        if (t == 0) running_s += total;
        __syncthreads();
    }
}

__global__ void fill_kernel(const int* __restrict__ src, const int* __restrict__ dst,
                            int* __restrict__ cursor, int* __restrict__ col) {
    int e = blockIdx.x * blockDim.x + threadIdx.x;
    if (e < N_EDGES) {
        int d = dst[e];
        int p = atomicAdd(&cursor[d], 1);
        col[p] = src[e];
    }
}

// ---------------- gather-mean: one warp per node, fp16 feature reads ----------
__global__ void gather16_kernel(const __half* __restrict__ feat16,
                                const int* __restrict__ row_start,
                                const int* __restrict__ degi,
                                const int* __restrict__ col,
                                float* __restrict__ agg) {
    int warp = (blockIdx.x * blockDim.x + threadIdx.x) >> 5;
    if (warp >= N_NODES) return;
    const int lane = threadIdx.x & 31;
    const int c4 = lane << 2;             // 4 halves per lane (8B loads)
    const int start = row_start[warp];
    const int len = degi[warp];
    const int end = start + len;

    float4 accA = make_float4(0.f, 0.f, 0.f, 0.f);
    float4 accB = make_float4(0.f, 0.f, 0.f, 0.f);
    int e = start;
    for (; e + 8 <= end; e += 8) {
        int s[8];
#pragma unroll
        for (int u = 0; u < 8; u++) s[u] = __ldg(&col[e + u]);
        uint2 v[8];
#pragma unroll
        for (int u = 0; u < 8; u++)
            v[u] = *(const uint2*)(feat16 + (size_t)s[u] * D + c4);
#pragma unroll
        for (int u = 0; u < 4; u++) {
            float2 f0 = __half22float2(*(__half2*)&v[u].x);
            float2 f1 = __half22float2(*(__half2*)&v[u].y);
            accA.x += f0.x; accA.y += f0.y; accA.z += f1.x; accA.w += f1.y;
            float2 g0 = __half22float2(*(__half2*)&v[u + 4].x);
            float2 g1 = __half22float2(*(__half2*)&v[u + 4].y);
            accB.x += g0.x; accB.y += g0.y; accB.z += g1.x; accB.w += g1.y;
        }
    }
    for (; e < end; e++) {
        int s = __ldg(&col[e]);
        uint2 v = *(const uint2*)(feat16 + (size_t)s * D + c4);
        float2 f0 = __half22float2(*(__half2*)&v.x);
        float2 f1 = __half22float2(*(__half2*)&v.y);
        accA.x += f0.x; accA.y += f0.y; accA.z += f1.x; accA.w += f1.y;
    }
    const float inv = 1.0f / fmaxf((float)len, 1.0f);
    float4 o;
    o.x = (accA.x + accB.x) * inv; o.y = (accA.y + accB.y) * inv;
    o.z = (accA.z + accB.z) * inv; o.w = (accA.w + accB.w) * inv;
    __stcs((float4*)(agg + (size_t)warp * D + c4), o);
}

// ---------------- weight transpose/concat ----------------
__global__ void wcat_kernel(const float* __restrict__ Ws, const float* __restrict__ Wn,
                            float* __restrict__ wcat) {
    int idx = blockIdx.x * blockDim.x + threadIdx.x;
    if (idx >= D * KTOT) return;
    int j = idx >> 8;
    int k = idx & 255;
    float v = (k < D) ? Ws[j * D + k] : Wn[j * D + (k - D)];
    wcat[k * D + j] = v;
}

// ---------------- fused SAGE GEMM: 128 thr, 8 rows x 8 cols / thread --------
// out16 != nullptr => also write fp16 copy of the output (pre-normalization
// never happens together: layer1 has do_norm=0 and writes out16).
__global__ void __launch_bounds__(GEMM_THREADS, 1)
sage_gemm_kernel(const float* __restrict__ feat,
                 const float* __restrict__ wcat,
                 const float* __restrict__ bias,
                 const float* __restrict__ agg,
                 float* __restrict__ out,
                 __half* __restrict__ out16,
                 int do_norm) {
    extern __shared__ float smem[];
    float* sw   = smem;                  // [256][128]
    float* sinp = smem + KTOT * D;       // [64][IRS]
    float* sb   = sinp + TILE_R * IRS;   // [128]

    const int tid = threadIdx.x;

    {
        const float4* wsrc = (const float4*)wcat;
        float4* wdst = (float4*)sw;
#pragma unroll 4
        for (int i = tid; i < (KTOT * D) / 4; i += GEMM_THREADS) wdst[i] = wsrc[i];
    }
    if (tid < D) sb[tid] = bias[tid];
    __syncthreads();

    const int ct = tid & 15;      // 16 col groups x 8 cols
    const int rt = tid >> 4;      // 8 row groups x 8 rows
    const int j0 = ct * 8;
    const int r0 = rt * 8;
    const int NT = (N_NODES + TILE_R - 1) / TILE_R;

    for (int tile = blockIdx.x; tile < NT; tile += gridDim.x) {
        const int row0 = tile * TILE_R;

#pragma unroll 4
        for (int idx = tid; idx < TILE_R * (KTOT / 4); idx += GEMM_THREADS) {
            int r = idx >> 6;
            int q = idx & 63;
            int grow = row0 + r;
            float4 v = make_float4(0.f, 0.f, 0.f, 0.f);
            if (grow < N_NODES) {
                if (q < 32)
                    v = *(const float4*)(feat + (size_t)grow * D + (q << 2));
                else
                    v = __ldcs((const float4*)(agg + (size_t)grow * D + ((q - 32) << 2)));
            }
            *(float4*)(sinp + r * IRS + (q << 2)) = v;
        }
        __syncthreads();

        unsigned long long acc[32];
#pragma unroll
        for (int i = 0; i < 32; i++) acc[i] = 0ull;

        const float* a0 = sinp + r0 * IRS;
        for (int k = 0; k < KTOT; k += 2) {
            float2 a2[8];
#pragma unroll
            for (int r = 0; r < 8; r++)
                a2[r] = *(const float2*)(a0 + r * IRS + k);

            const float* wk0 = sw + (k << 7) + j0;
            ulonglong2 wA0 = *(const ulonglong2*)(wk0);
            ulonglong2 wB0 = *(const ulonglong2*)(wk0 + 4);
            const float* wk1 = wk0 + D;
            ulonglong2 wA1 = *(const ulonglong2*)(wk1);
            ulonglong2 wB1 = *(const ulonglong2*)(wk1 + 4);
#pragma unroll
            for (int r = 0; r < 8; r++) {
                unsigned long long av0 = pack2(a2[r].x);
                acc[r * 4 + 0] = ffma2(av0, wA0.x, acc[r * 4 + 0]);
                acc[r * 4 + 1] = ffma2(av0, wA0.y, acc[r * 4 + 1]);
                acc[r * 4 + 2] = ffma2(av0, wB0.x, acc[r * 4 + 2]);
                acc[r * 4 + 3] = ffma2(av0, wB0.y, acc[r * 4 + 3]);
            }
#pragma unroll
            for (int r = 0; r < 8; r++) {
                unsigned long long av1 = pack2(a2[r].y);
                acc[r * 4 + 0] = ffma2(av1, wA1.x, acc[r * 4 + 0]);
                acc[r * 4 + 1] = ffma2(av1, wA1.y, acc[r * 4 + 1]);
                acc[r * 4 + 2] = ffma2(av1, wB1.x, acc[r * 4 + 2]);
                acc[r * 4 + 3] = ffma2(av1, wB1.y, acc[r * 4 + 3]);
            }
        }

#pragma unroll
        for (int r = 0; r < 8; ++r) {
            float v[8];
            float2 t;
            t = unpack2(acc[r * 4 + 0]); v[0] = t.x; v[1] = t.y;
            t = unpack2(acc[r * 4 + 1]); v[2] = t.x; v[3] = t.y;
            t = unpack2(acc[r * 4 + 2]); v[4] = t.x; v[5] = t.y;
            t = unpack2(acc[r * 4 + 3]); v[6] = t.x; v[7] = t.y;
#pragma unroll
            for (int c = 0; c < 8; c++) v[c] += sb[j0 + c];

            float scale = 1.0f;
            if (do_norm) {
                float ss = 0.f;
#pragma unroll
                for (int c = 0; c < 8; c++) ss += v[c] * v[c];
#pragma unroll
                for (int m = 8; m >= 1; m >>= 1)
                    ss += __shfl_xor_sync(0xffffffffu, ss, m);
                scale = 1.0f / fmaxf(sqrtf(ss), 1e-12f);
            }

            int grow = row0 + r0 + r;
            if (grow < N_NODES) {
                float* op = out + (size_t)grow * D + j0;
                float4 o;
                o.x = v[0] * scale; o.y = v[1] * scale;
                o.z = v[2] * scale; o.w = v[3] * scale;
                if (do_norm) __stcs((float4*)op, o); else *(float4*)op = o;
                float4 o2;
                o2.x = v[4] * scale; o2.y = v[5] * scale;
                o2.z = v[6] * scale; o2.w = v[7] * scale;
                if (do_norm) __stcs((float4*)(op + 4), o2); else *(float4*)(op + 4) = o2;

                if (out16) {
                    __half2 p0 = __floats2half2_rn(o.x, o.y);
                    __half2 p1 = __floats2half2_rn(o.z, o.w);
                    __half2 p2 = __floats2half2_rn(o2.x, o2.y);
                    __half2 p3 = __floats2half2_rn(o2.z, o2.w);
                    uint4 u = make_uint4(*(unsigned*)&p0, *(unsigned*)&p1,
                                         *(unsigned*)&p2, *(unsigned*)&p3);
                    *(uint4*)(out16 + (size_t)grow * D + j0) = u;
                }
            }
        }
        __syncthreads();
    }
}

// ---------------- launch ----------------
extern "C" void kernel_launch(void* const* d_in, const int* in_sizes, int n_in,
                              void* d_out, int out_size) {
    const float* x   = (const float*)d_in[0];
    const int* src   = (const int*)d_in[1];
    const int* dst   = (const int*)d_in[2];
    const float* Ws1 = (const float*)d_in[3];
    const float* Wn1 = (const float*)d_in[4];
    const float* b1  = (const float*)d_in[5];
    const float* Ws2 = (const float*)d_in[6];
    const float* Wn2 = (const float*)d_in[7];
    const float* b2  = (const float*)d_in[8];
    float* out = (float*)d_out;

    float* agg;    cudaGetSymbolAddress((void**)&agg, g_agg);
    float* h1;     cudaGetSymbolAddress((void**)&h1, g_h1);
    __half* f16;   cudaGetSymbolAddress((void**)&f16, g_f16);
    float* wcat1;  cudaGetSymbolAddress((void**)&wcat1, g_wcat1);
    float* wcat2;  cudaGetSymbolAddress((void**)&wcat2, g_wcat2);
    int* degi;     cudaGetSymbolAddress((void**)&degi, g_degi);
    int* rowst;    cudaGetSymbolAddress((void**)&rowst, g_rowstart);
    int* cursor;   cudaGetSymbolAddress((void**)&cursor, g_cursor);
    int* col;      cudaGetSymbolAddress((void**)&col, g_col);

    int sms = 148;
    cudaDeviceGetAttribute(&sms, cudaDevAttrMultiProcessorCount, 0);
    cudaFuncSetAttribute(sage_gemm_kernel,
                         cudaFuncAttributeMaxDynamicSharedMemorySize, SMEM_BYTES);

    const int GATHER_BLOCKS = (N_NODES * 32 + 255) / 256;
    const int CVT_ITEMS = N_NODES * D / 4;   // 3.2M (covers N_EDGES too)

    // degi zero via memset (not a kernel launch -> keeps gather at launch #4)
    cudaMemsetAsync(degi, 0, N_NODES * sizeof(int));

    // #1: degree histogram + x -> fp16
    degx2h_kernel<<<(CVT_ITEMS + 255) / 256, 256>>>(dst, degi, x, f16);
    // #2: exclusive scan -> rowstart/cursor
    scan_kernel<<<1, 1024>>>(degi, rowst, cursor);
    // #3: CSR fill
    fill_kernel<<<(N_EDGES + 255) / 256, 256>>>(src, dst, cursor, col);
    // #4: layer-1 gather  (ncu capture lands here)
    gather16_kernel<<<GATHER_BLOCKS, 256>>>(f16, rowst, degi, col, agg);

    // weights
    wcat_kernel<<<(KTOT * D + 255) / 256, 256>>>(Ws1, Wn1, wcat1);
    wcat_kernel<<<(KTOT * D + 255) / 256, 256>>>(Ws2, Wn2, wcat2);

    // layer-1 GEMM: writes h1 fp32 + f16 (fp16 shadow for layer-2 gather)
    sage_gemm_kernel<<<sms, GEMM_THREADS, SMEM_BYTES>>>(x, wcat1, b1, agg, h1, f16, 0);

    // layer 2
    gather16_kernel<<<GATHER_BLOCKS, 256>>>(f16, rowst, degi, col, agg);
    sage_gemm_kernel<<<sms, GEMM_THREADS, SMEM_BYTES>>>(h1, wcat2, b2, agg, out, ((__half*)0), 1);
}

// round 10
// speedup vs baseline: 3.1276x; 2.8844x over previous
#include <cuda_runtime.h>
#include <cuda_fp16.h>
#include <cstdint>

#define N_NODES 100000
#define N_EDGES 1600000
#define D 128
#define TILE_R 64
#define SA_K 264                     // padded k-stride (halves): LDSM conflict-free
#define MMA_THREADS 256
// smem: A[64][264]h + B[128][264]h + bias[128]f + snorm[64*2]f
#define SMEM_MMA (TILE_R*SA_K*2 + 128*SA_K*2 + 128*4 + 128*4)   // 102400

// ---------------- device scratch ----------------
__device__ __align__(16) float  g_agg[(size_t)N_NODES * D];
__device__ __align__(16) __half g_f16[(size_t)N_NODES * D];   // fp16 shadow of layer input
__device__ __align__(16) int    g_degi[N_NODES];
__device__ __align__(16) int    g_rowstart[N_NODES];
__device__ __align__(16) int    g_cursor[N_NODES];
__device__ __align__(16) int    g_col[N_EDGES];

// ---------------- mma helpers ----------------
__device__ __forceinline__ uint32_t smem_u32(const void* p) {
    uint32_t a;
    asm("{ .reg .u64 t; cvta.to.shared.u64 t, %1; cvt.u32.u64 %0, t; }" : "=r"(a) : "l"(p));
    return a;
}
__device__ __forceinline__ void ldsm_x4(uint32_t& r0, uint32_t& r1, uint32_t& r2,
                                        uint32_t& r3, uint32_t addr) {
    asm volatile("ldmatrix.sync.aligned.m8n8.x4.shared.b16 {%0,%1,%2,%3}, [%4];"
                 : "=r"(r0), "=r"(r1), "=r"(r2), "=r"(r3) : "r"(addr));
}
__device__ __forceinline__ void mma16816(float* d, const uint32_t* a,
                                         uint32_t b0, uint32_t b1) {
    asm volatile(
        "mma.sync.aligned.m16n8k16.row.col.f32.f16.f16.f32 "
        "{%0,%1,%2,%3}, {%4,%5,%6,%7}, {%8,%9}, {%0,%1,%2,%3};"
        : "+f"(d[0]), "+f"(d[1]), "+f"(d[2]), "+f"(d[3])
        : "r"(a[0]), "r"(a[1]), "r"(a[2]), "r"(a[3]), "r"(b0), "r"(b1));
}
__device__ __forceinline__ uint32_t h2u(__half2 h) { return *(uint32_t*)&h; }

// ---------------- fused degree histogram + x -> fp16 conversion ----------------
__global__ void degx2h_kernel(const int* __restrict__ dst, int* __restrict__ degi,
                              const float* __restrict__ x, __half* __restrict__ x16) {
    int i = blockIdx.x * blockDim.x + threadIdx.x;
    if (i < N_EDGES) atomicAdd(&degi[dst[i]], 1);
    if (i < N_NODES * D / 4) {
        float4 v = *(const float4*)(x + (size_t)i * 4);
        __half2 a = __floats2half2_rn(v.x, v.y);
        __half2 b = __floats2half2_rn(v.z, v.w);
        *(uint2*)(x16 + (size_t)i * 4) = make_uint2(h2u(a), h2u(b));
    }
}

// ---------------- single-block pass-based exclusive scan ----------------
__global__ void scan_kernel(const int* __restrict__ deg,
                            int* __restrict__ rowstart, int* __restrict__ cursor) {
    __shared__ int wsums[32];
    __shared__ int running_s;
    const int t = threadIdx.x;
    const int lane = t & 31, w = t >> 5;
    if (t == 0) running_s = 0;
    __syncthreads();

    for (int base = 0; base < N_NODES; base += 4096) {
        int i0 = base + t * 4;
        int4 d4 = make_int4(0, 0, 0, 0);
        if (i0 + 3 < N_NODES) d4 = *(const int4*)(deg + i0);
        else {
            if (i0 + 0 < N_NODES) d4.x = deg[i0 + 0];
            if (i0 + 1 < N_NODES) d4.y = deg[i0 + 1];
            if (i0 + 2 < N_NODES) d4.z = deg[i0 + 2];
        }
        int tsum = d4.x + d4.y + d4.z + d4.w;
        int sc = tsum;
#pragma unroll
        for (int m = 1; m < 32; m <<= 1) {
            int u = __shfl_up_sync(0xffffffffu, sc, m);
            if (lane >= m) sc += u;
        }
        if (lane == 31) wsums[w] = sc;
        __syncthreads();
        if (w == 0) {
            int s2 = wsums[lane];
#pragma unroll
            for (int m = 1; m < 32; m <<= 1) {
                int u = __shfl_up_sync(0xffffffffu, s2, m);
                if (lane >= m) s2 += u;
            }
            wsums[lane] = s2;
        }
        __syncthreads();
        int excl = running_s + (w > 0 ? wsums[w - 1] : 0) + sc - tsum;
        int r = excl;
        if (i0 + 0 < N_NODES) { rowstart[i0 + 0] = r; cursor[i0 + 0] = r; } r += d4.x;
        if (i0 + 1 < N_NODES) { rowstart[i0 + 1] = r; cursor[i0 + 1] = r; } r += d4.y;
        if (i0 + 2 < N_NODES) { rowstart[i0 + 2] = r; cursor[i0 + 2] = r; } r += d4.z;
        if (i0 + 3 < N_NODES) { rowstart[i0 + 3] = r; cursor[i0 + 3] = r; }
        int total = wsums[31];
        __syncthreads();
        if (t == 0) running_s += total;
        __syncthreads();
    }
}

__global__ void fill_kernel(const int* __restrict__ src, const int* __restrict__ dst,
                            int* __restrict__ cursor, int* __restrict__ col) {
    int e = blockIdx.x * blockDim.x + threadIdx.x;
    if (e < N_EDGES) {
        int d = dst[e];
        int p = atomicAdd(&cursor[d], 1);
        col[p] = src[e];
    }
}

// ---------------- gather-mean: one warp per node, fp16 feature reads ----------
// Writes the MEAN (sum / deg) into agg.
__global__ void gather16_kernel(const __half* __restrict__ feat16,
                                const int* __restrict__ row_start,
                                const int* __restrict__ degi,
                                const int* __restrict__ col,
                                float* __restrict__ agg) {
    int warp = (blockIdx.x * blockDim.x + threadIdx.x) >> 5;
    if (warp >= N_NODES) return;
    const int lane = threadIdx.x & 31;
    const int c4 = lane << 2;
    const int start = row_start[warp];
    const int len = degi[warp];
    const int end = start + len;

    float4 accA = make_float4(0.f, 0.f, 0.f, 0.f);
    float4 accB = make_float4(0.f, 0.f, 0.f, 0.f);
    int e = start;
    for (; e + 8 <= end; e += 8) {
        int s[8];
#pragma unroll
        for (int u = 0; u < 8; u++) s[u] = __ldg(&col[e + u]);
        uint2 v[8];
#pragma unroll
        for (int u = 0; u < 8; u++)
            v[u] = *(const uint2*)(feat16 + (size_t)s[u] * D + c4);
#pragma unroll
        for (int u = 0; u < 4; u++) {
            float2 f0 = __half22float2(*(__half2*)&v[u].x);
            float2 f1 = __half22float2(*(__half2*)&v[u].y);
            accA.x += f0.x; accA.y += f0.y; accA.z += f1.x; accA.w += f1.y;
            float2 g0 = __half22float2(*(__half2*)&v[u + 4].x);
            float2 g1 = __half22float2(*(__half2*)&v[u + 4].y);
            accB.x += g0.x; accB.y += g0.y; accB.z += g1.x; accB.w += g1.y;
        }
    }
    for (; e < end; e++) {
        int s = __ldg(&col[e]);
        uint2 v = *(const uint2*)(feat16 + (size_t)s * D + c4);
        float2 f0 = __half22float2(*(__half2*)&v.x);
        float2 f1 = __half22float2(*(__half2*)&v.y);
        accA.x += f0.x; accA.y += f0.y; accA.z += f1.x; accA.w += f1.y;
    }
    const float inv = 1.0f / fmaxf((float)len, 1.0f);
    float4 o;
    o.x = (accA.x + accB.x) * inv; o.y = (accA.y + accB.y) * inv;
    o.z = (accA.z + accB.z) * inv; o.w = (accA.w + accB.w) * inv;
    __stcs((float4*)(agg + (size_t)warp * D + c4), o);
}

// ---------------- tensor-core SAGE layer ----------------
// out[r][n] = sum_k A[r][k] * Wcat[n][k] + b[n]  (+ optional row L2-norm)
// A = [f16feat | fp16(agg_mean)] staged per 64-row tile; Wcat = [Ws|Wn] fp16.
// 8 warps: warp_m = wid&3 (16 rows), warp_n = wid>>2 (64 cols).
__global__ void __launch_bounds__(MMA_THREADS, 2)
sage_mma_kernel(const __half* __restrict__ f16feat,
                const float* __restrict__ agg,      // already the MEAN
                const float* __restrict__ Ws,
                const float* __restrict__ Wn,
                const float* __restrict__ bias,
                float* __restrict__ out,       // may be null (layer 1)
                __half* __restrict__ out16,    // may be null (layer 2)
                int do_norm) {
    extern __shared__ __half sh[];
    __half* sA = sh;                          // [64][SA_K]
    __half* sB = sh + TILE_R * SA_K;          // [128][SA_K]
    float* sbias = (float*)(sB + 128 * SA_K); // [128]
    float* snorm = sbias + 128;               // [64][2]

    const int tid = threadIdx.x;
    const int wid = tid >> 5;
    const int lane = tid & 31;
    const int warp_m = wid & 3;
    const int warp_n = wid >> 2;

    // ---- stage B (weights) once: row n=j, k in [0,256) ----
    {
        int j = tid >> 1;
        int kh = (tid & 1) * 128;
        const float* W = (tid & 1) ? Wn : Ws;
        const float4* wr = (const float4*)(W + j * D);
        uint4* drow = (uint4*)(sB + j * SA_K + kh);
#pragma unroll 4
        for (int q = 0; q < 16; q++) {
            float4 v0 = wr[q * 2], v1 = wr[q * 2 + 1];
            drow[q] = make_uint4(h2u(__floats2half2_rn(v0.x, v0.y)),
                                 h2u(__floats2half2_rn(v0.z, v0.w)),
                                 h2u(__floats2half2_rn(v1.x, v1.y)),
                                 h2u(__floats2half2_rn(v1.z, v1.w)));
        }
    }
    if (tid < 128) sbias[tid] = bias[tid];

    const uint32_t sA_addr = smem_u32(sA);
    const uint32_t sB_addr = smem_u32(sB);
    const uint32_t a_base = sA_addr + ((warp_m * 16 + (lane & 15)) * SA_K + (lane >> 4) * 8) * 2;
    const uint32_t b_row = warp_n * 64 + (lane & 15);
    const uint32_t b_base = sB_addr + (b_row * SA_K + (lane >> 4) * 8) * 2;

    const int NT = (N_NODES + TILE_R - 1) / TILE_R;

    for (int tile = blockIdx.x; tile < NT; tile += gridDim.x) {
        const int row0 = tile * TILE_R;

        // ---- stage A tile: row r = tid>>2, quarter q = tid&3 (64 halves each) ----
        {
            int r = tid >> 2, q = tid & 3;
            int grow = row0 + r;
            uint4* dd = (uint4*)(sA + r * SA_K + q * 64);
            if (grow < N_NODES) {
                if (q < 2) {
                    const uint4* s = (const uint4*)(f16feat + (size_t)grow * D + q * 64);
#pragma unroll
                    for (int i = 0; i < 8; i++) dd[i] = s[i];
                } else {
                    // agg already holds the mean — NO division here
                    const float4* s = (const float4*)(agg + (size_t)grow * D + (q - 2) * 64);
#pragma unroll
                    for (int i = 0; i < 8; i++) {
                        float4 v0 = s[i * 2], v1 = s[i * 2 + 1];
                        dd[i] = make_uint4(
                            h2u(__floats2half2_rn(v0.x, v0.y)),
                            h2u(__floats2half2_rn(v0.z, v0.w)),
                            h2u(__floats2half2_rn(v1.x, v1.y)),
                            h2u(__floats2half2_rn(v1.z, v1.w)));
                    }
                }
            } else {
                uint4 z = make_uint4(0, 0, 0, 0);
#pragma unroll
                for (int i = 0; i < 8; i++) dd[i] = z;
            }
        }
        __syncthreads();

        // ---- mma mainloop: K = 256 in 16 k16 steps ----
        float acc[8][4];
#pragma unroll
        for (int i = 0; i < 8; i++)
#pragma unroll
            for (int j = 0; j < 4; j++) acc[i][j] = 0.f;

#pragma unroll 4
        for (int ks = 0; ks < 16; ks++) {
            uint32_t a[4];
            ldsm_x4(a[0], a[1], a[2], a[3], a_base + ks * 32);
#pragma unroll
            for (int nf2 = 0; nf2 < 4; nf2++) {
                uint32_t b0, b1, b2, b3;
                ldsm_x4(b0, b1, b2, b3, b_base + nf2 * 16 * SA_K * 2 + ks * 32);
                mma16816(acc[nf2 * 2 + 0], a, b0, b2);
                mma16816(acc[nf2 * 2 + 1], a, b1, b3);
            }
        }

        // ---- epilogue: bias + (optional) cross-warp-pair L2 norm ----
        const int tg = lane & 3;
        const int rr = lane >> 2;
        const int row_a = warp_m * 16 + rr;
        const int row_b = row_a + 8;

        float ss_a = 0.f, ss_b = 0.f;
#pragma unroll
        for (int nf = 0; nf < 8; nf++) {
            int n0 = warp_n * 64 + nf * 8 + tg * 2;
            acc[nf][0] += sbias[n0]; acc[nf][1] += sbias[n0 + 1];
            acc[nf][2] += sbias[n0]; acc[nf][3] += sbias[n0 + 1];
            ss_a += acc[nf][0] * acc[nf][0] + acc[nf][1] * acc[nf][1];
            ss_b += acc[nf][2] * acc[nf][2] + acc[nf][3] * acc[nf][3];
        }
        ss_a += __shfl_xor_sync(0xffffffffu, ss_a, 1);
        ss_a += __shfl_xor_sync(0xffffffffu, ss_a, 2);
        ss_b += __shfl_xor_sync(0xffffffffu, ss_b, 1);
        ss_b += __shfl_xor_sync(0xffffffffu, ss_b, 2);

        float scale_a = 1.f, scale_b = 1.f;
        if (do_norm) {
            if (tg == 0) {
                snorm[row_a * 2 + warp_n] = ss_a;
                snorm[row_b * 2 + warp_n] = ss_b;
            }
            __syncthreads();
            float fa = snorm[row_a * 2 + 0] + snorm[row_a * 2 + 1];
            float fb = snorm[row_b * 2 + 0] + snorm[row_b * 2 + 1];
            scale_a = 1.0f / fmaxf(sqrtf(fa), 1e-12f);
            scale_b = 1.0f / fmaxf(sqrtf(fb), 1e-12f);
        } else {
            __syncthreads();   // mma-complete barrier before next tile's staging
        }

        int grow_a = row0 + row_a;
        int grow_b = row0 + row_b;
#pragma unroll
        for (int nf = 0; nf < 8; nf++) {
            int n0 = warp_n * 64 + nf * 8 + tg * 2;
            if (grow_a < N_NODES) {
                float v0 = acc[nf][0] * scale_a, v1 = acc[nf][1] * scale_a;
                if (out) *(float2*)(out + (size_t)grow_a * D + n0) = make_float2(v0, v1);
                if (out16) *(__half2*)(out16 + (size_t)grow_a * D + n0) = __floats2half2_rn(v0, v1);
            }
            if (grow_b < N_NODES) {
                float v0 = acc[nf][2] * scale_b, v1 = acc[nf][3] * scale_b;
                if (out) *(float2*)(out + (size_t)grow_b * D + n0) = make_float2(v0, v1);
                if (out16) *(__half2*)(out16 + (size_t)grow_b * D + n0) = __floats2half2_rn(v0, v1);
            }
        }
        __syncthreads();   // writes done before sA restaged
    }
}

// ---------------- launch ----------------
extern "C" void kernel_launch(void* const* d_in, const int* in_sizes, int n_in,
                              void* d_out, int out_size) {
    const float* x   = (const float*)d_in[0];
    const int* src   = (const int*)d_in[1];
    const int* dst   = (const int*)d_in[2];
    const float* Ws1 = (const float*)d_in[3];
    const float* Wn1 = (const float*)d_in[4];
    const float* b1  = (const float*)d_in[5];
    const float* Ws2 = (const float*)d_in[6];
    const float* Wn2 = (const float*)d_in[7];
    const float* b2  = (const float*)d_in[8];
    float* out = (float*)d_out;

    float* agg;    cudaGetSymbolAddress((void**)&agg, g_agg);
    __half* f16;   cudaGetSymbolAddress((void**)&f16, g_f16);
    int* degi;     cudaGetSymbolAddress((void**)&degi, g_degi);
    int* rowst;    cudaGetSymbolAddress((void**)&rowst, g_rowstart);
    int* cursor;   cudaGetSymbolAddress((void**)&cursor, g_cursor);
    int* col;      cudaGetSymbolAddress((void**)&col, g_col);

    int sms = 148;
    cudaDeviceGetAttribute(&sms, cudaDevAttrMultiProcessorCount, 0);
    cudaFuncSetAttribute(sage_mma_kernel,
                         cudaFuncAttributeMaxDynamicSharedMemorySize, SMEM_MMA);

    const int GATHER_BLOCKS = (N_NODES * 32 + 255) / 256;
    const int CVT_ITEMS = N_NODES * D / 4;

    cudaMemsetAsync(degi, 0, N_NODES * sizeof(int));

    // #1: degree histogram + x -> fp16
    degx2h_kernel<<<(CVT_ITEMS + 255) / 256, 256>>>(dst, degi, x, f16);
    // #2: exclusive scan
    scan_kernel<<<1, 1024>>>(degi, rowst, cursor);
    // #3: CSR fill
    fill_kernel<<<(N_EDGES + 255) / 256, 256>>>(src, dst, cursor, col);
    // #4: layer-1 gather (ncu capture control)
    gather16_kernel<<<GATHER_BLOCKS, 256>>>(f16, rowst, degi, col, agg);
    // #5: layer-1 tensor GEMM -> fp16 shadow only
    sage_mma_kernel<<<2 * sms, MMA_THREADS, SMEM_MMA>>>(
        f16, agg, Ws1, Wn1, b1, (float*)0, f16, 0);
    // #6: layer-2 gather
    gather16_kernel<<<GATHER_BLOCKS, 256>>>(f16, rowst, degi, col, agg);
    // #7: layer-2 tensor GEMM -> fp32 out with L2 norm
    sage_mma_kernel<<<2 * sms, MMA_THREADS, SMEM_MMA>>>(
        f16, agg, Ws2, Wn2, b2, out, (__half*)0, 1);
}

// round 11
// speedup vs baseline: 3.2746x; 1.0470x over previous
#include <cuda_runtime.h>
#include <cuda_fp16.h>
#include <cstdint>

#define N_NODES 100000
#define N_EDGES 1600000
#define D 128
#define TILE_R 64
#define SA_K 264                     // padded k-stride (halves): LDSM conflict-free
#define MMA_THREADS 256
// smem: A[64][264]h + B[128][264]h + bias[128]f + snorm[64*2]f
#define SMEM_MMA (TILE_R*SA_K*2 + 128*SA_K*2 + 128*4 + 128*4)   // 102400

// ---------------- device scratch ----------------
__device__ __align__(16) __half g_agg16[(size_t)N_NODES * D];  // fp16 neighbor mean
__device__ __align__(16) __half g_f16[(size_t)N_NODES * D];    // fp16 shadow of layer input
__device__ __align__(16) int    g_degi[N_NODES];
__device__ __align__(16) int    g_rowstart[N_NODES];
__device__ __align__(16) int    g_cursor[N_NODES];
__device__ __align__(16) int    g_col[N_EDGES];

// ---------------- mma helpers ----------------
__device__ __forceinline__ uint32_t smem_u32(const void* p) {
    uint32_t a;
    asm("{ .reg .u64 t; cvta.to.shared.u64 t, %1; cvt.u32.u64 %0, t; }" : "=r"(a) : "l"(p));
    return a;
}
__device__ __forceinline__ void ldsm_x4(uint32_t& r0, uint32_t& r1, uint32_t& r2,
                                        uint32_t& r3, uint32_t addr) {
    asm volatile("ldmatrix.sync.aligned.m8n8.x4.shared.b16 {%0,%1,%2,%3}, [%4];"
                 : "=r"(r0), "=r"(r1), "=r"(r2), "=r"(r3) : "r"(addr));
}
__device__ __forceinline__ void mma16816(float* d, const uint32_t* a,
                                         uint32_t b0, uint32_t b1) {
    asm volatile(
        "mma.sync.aligned.m16n8k16.row.col.f32.f16.f16.f32 "
        "{%0,%1,%2,%3}, {%4,%5,%6,%7}, {%8,%9}, {%0,%1,%2,%3};"
        : "+f"(d[0]), "+f"(d[1]), "+f"(d[2]), "+f"(d[3])
        : "r"(a[0]), "r"(a[1]), "r"(a[2]), "r"(a[3]), "r"(b0), "r"(b1));
}
__device__ __forceinline__ uint32_t h2u(__half2 h) { return *(uint32_t*)&h; }

// ---------------- fused degree histogram + x -> fp16 conversion ----------------
__global__ void degx2h_kernel(const int* __restrict__ dst, int* __restrict__ degi,
                              const float* __restrict__ x, __half* __restrict__ x16) {
    int i = blockIdx.x * blockDim.x + threadIdx.x;
    if (i < N_EDGES) atomicAdd(&degi[dst[i]], 1);
    if (i < N_NODES * D / 4) {
        float4 v = *(const float4*)(x + (size_t)i * 4);
        __half2 a = __floats2half2_rn(v.x, v.y);
        __half2 b = __floats2half2_rn(v.z, v.w);
        *(uint2*)(x16 + (size_t)i * 4) = make_uint2(h2u(a), h2u(b));
    }
}

// ---------------- single-block pass-based exclusive scan ----------------
__global__ void scan_kernel(const int* __restrict__ deg,
                            int* __restrict__ rowstart, int* __restrict__ cursor) {
    __shared__ int wsums[32];
    __shared__ int running_s;
    const int t = threadIdx.x;
    const int lane = t & 31, w = t >> 5;
    if (t == 0) running_s = 0;
    __syncthreads();

    for (int base = 0; base < N_NODES; base += 4096) {
        int i0 = base + t * 4;
        int4 d4 = make_int4(0, 0, 0, 0);
        if (i0 + 3 < N_NODES) d4 = *(const int4*)(deg + i0);
        else {
            if (i0 + 0 < N_NODES) d4.x = deg[i0 + 0];
            if (i0 + 1 < N_NODES) d4.y = deg[i0 + 1];
            if (i0 + 2 < N_NODES) d4.z = deg[i0 + 2];
        }
        int tsum = d4.x + d4.y + d4.z + d4.w;
        int sc = tsum;
#pragma unroll
        for (int m = 1; m < 32; m <<= 1) {
            int u = __shfl_up_sync(0xffffffffu, sc, m);
            if (lane >= m) sc += u;
        }
        if (lane == 31) wsums[w] = sc;
        __syncthreads();
        if (w == 0) {
            int s2 = wsums[lane];
#pragma unroll
            for (int m = 1; m < 32; m <<= 1) {
                int u = __shfl_up_sync(0xffffffffu, s2, m);
                if (lane >= m) s2 += u;
            }
            wsums[lane] = s2;
        }
        __syncthreads();
        int excl = running_s + (w > 0 ? wsums[w - 1] : 0) + sc - tsum;
        int r = excl;
        if (i0 + 0 < N_NODES) { rowstart[i0 + 0] = r; cursor[i0 + 0] = r; } r += d4.x;
        if (i0 + 1 < N_NODES) { rowstart[i0 + 1] = r; cursor[i0 + 1] = r; } r += d4.y;
        if (i0 + 2 < N_NODES) { rowstart[i0 + 2] = r; cursor[i0 + 2] = r; } r += d4.z;
        if (i0 + 3 < N_NODES) { rowstart[i0 + 3] = r; cursor[i0 + 3] = r; }
        int total = wsums[31];
        __syncthreads();
        if (t == 0) running_s += total;
        __syncthreads();
    }
}

__global__ void fill_kernel(const int* __restrict__ src, const int* __restrict__ dst,
                            int* __restrict__ cursor, int* __restrict__ col) {
    int e = blockIdx.x * blockDim.x + threadIdx.x;
    if (e < N_EDGES) {
        int d = dst[e];
        int p = atomicAdd(&cursor[d], 1);
        col[p] = src[e];
    }
}

// ---------------- gather-mean: one warp per node, fp16 in, fp16 out ----------
// Accumulates in fp32, stores the MEAN as fp16 (same rounding the GEMM staging
// previously applied -> bit-identical downstream).
__global__ void gather16_kernel(const __half* __restrict__ feat16,
                                const int* __restrict__ row_start,
                                const int* __restrict__ degi,
                                const int* __restrict__ col,
                                __half* __restrict__ agg16) {
    int warp = (blockIdx.x * blockDim.x + threadIdx.x) >> 5;
    if (warp >= N_NODES) return;
    const int lane = threadIdx.x & 31;
    const int c4 = lane << 2;
    const int start = row_start[warp];
    const int len = degi[warp];
    const int end = start + len;

    float4 accA = make_float4(0.f, 0.f, 0.f, 0.f);
    float4 accB = make_float4(0.f, 0.f, 0.f, 0.f);
    int e = start;
    for (; e + 8 <= end; e += 8) {
        int s[8];
#pragma unroll
        for (int u = 0; u < 8; u++) s[u] = __ldg(&col[e + u]);
        uint2 v[8];
#pragma unroll
        for (int u = 0; u < 8; u++)
            v[u] = *(const uint2*)(feat16 + (size_t)s[u] * D + c4);
#pragma unroll
        for (int u = 0; u < 4; u++) {
            float2 f0 = __half22float2(*(__half2*)&v[u].x);
            float2 f1 = __half22float2(*(__half2*)&v[u].y);
            accA.x += f0.x; accA.y += f0.y; accA.z += f1.x; accA.w += f1.y;
            float2 g0 = __half22float2(*(__half2*)&v[u + 4].x);
            float2 g1 = __half22float2(*(__half2*)&v[u + 4].y);
            accB.x += g0.x; accB.y += g0.y; accB.z += g1.x; accB.w += g1.y;
        }
    }
    for (; e < end; e++) {
        int s = __ldg(&col[e]);
        uint2 v = *(const uint2*)(feat16 + (size_t)s * D + c4);
        float2 f0 = __half22float2(*(__half2*)&v.x);
        float2 f1 = __half22float2(*(__half2*)&v.y);
        accA.x += f0.x; accA.y += f0.y; accA.z += f1.x; accA.w += f1.y;
    }
    const float inv = 1.0f / fmaxf((float)len, 1.0f);
    __half2 o0 = __floats2half2_rn((accA.x + accB.x) * inv, (accA.y + accB.y) * inv);
    __half2 o1 = __floats2half2_rn((accA.z + accB.z) * inv, (accA.w + accB.w) * inv);
    __stcs((uint2*)(agg16 + (size_t)warp * D + c4), make_uint2(h2u(o0), h2u(o1)));
}

// ---------------- tensor-core SAGE layer ----------------
// out[r][n] = sum_k A[r][k] * Wcat[n][k] + b[n]  (+ optional row L2-norm)
// A = [f16feat | agg16] staged per 64-row tile (pure fp16 copies); Wcat fp16.
// 8 warps: warp_m = wid&3 (16 rows), warp_n = wid>>2 (64 cols).
__global__ void __launch_bounds__(MMA_THREADS, 2)
sage_mma_kernel(const __half* __restrict__ f16feat,
                const __half* __restrict__ agg16,
                const float* __restrict__ Ws,
                const float* __restrict__ Wn,
                const float* __restrict__ bias,
                float* __restrict__ out,       // may be null (layer 1)
                __half* __restrict__ out16,    // may be null (layer 2)
                int do_norm) {
    extern __shared__ __half sh[];
    __half* sA = sh;                          // [64][SA_K]
    __half* sB = sh + TILE_R * SA_K;          // [128][SA_K]
    float* sbias = (float*)(sB + 128 * SA_K); // [128]
    float* snorm = sbias + 128;               // [64][2]

    const int tid = threadIdx.x;
    const int wid = tid >> 5;
    const int lane = tid & 31;
    const int warp_m = wid & 3;
    const int warp_n = wid >> 2;

    // ---- stage B (weights) once: row n=j, k in [0,256) ----
    {
        int j = tid >> 1;
        int kh = (tid & 1) * 128;
        const float* W = (tid & 1) ? Wn : Ws;
        const float4* wr = (const float4*)(W + j * D);
        uint4* drow = (uint4*)(sB + j * SA_K + kh);
#pragma unroll 4
        for (int q = 0; q < 16; q++) {
            float4 v0 = wr[q * 2], v1 = wr[q * 2 + 1];
            drow[q] = make_uint4(h2u(__floats2half2_rn(v0.x, v0.y)),
                                 h2u(__floats2half2_rn(v0.z, v0.w)),
                                 h2u(__floats2half2_rn(v1.x, v1.y)),
                                 h2u(__floats2half2_rn(v1.z, v1.w)));
        }
    }
    if (tid < 128) sbias[tid] = bias[tid];

    const uint32_t sA_addr = smem_u32(sA);
    const uint32_t sB_addr = smem_u32(sB);
    const uint32_t a_base = sA_addr + ((warp_m * 16 + (lane & 15)) * SA_K + (lane >> 4) * 8) * 2;
    const uint32_t b_row = warp_n * 64 + (lane & 15);
    const uint32_t b_base = sB_addr + (b_row * SA_K + (lane >> 4) * 8) * 2;

    const int NT = (N_NODES + TILE_R - 1) / TILE_R;

    for (int tile = blockIdx.x; tile < NT; tile += gridDim.x) {
        const int row0 = tile * TILE_R;

        // ---- stage A tile: row r = tid>>2, quarter q = tid&3 (64 halves each) ----
        {
            int r = tid >> 2, q = tid & 3;
            int grow = row0 + r;
            uint4* dd = (uint4*)(sA + r * SA_K + q * 64);
            if (grow < N_NODES) {
                const __half* src = (q < 2)
                    ? f16feat + (size_t)grow * D + q * 64
                    : agg16 + (size_t)grow * D + (q - 2) * 64;
                const uint4* s = (const uint4*)src;
#pragma unroll
                for (int i = 0; i < 8; i++) dd[i] = s[i];
            } else {
                uint4 z = make_uint4(0, 0, 0, 0);
#pragma unroll
                for (int i = 0; i < 8; i++) dd[i] = z;
            }
        }
        __syncthreads();

        // ---- mma mainloop: K = 256 in 16 k16 steps ----
        float acc[8][4];
#pragma unroll
        for (int i = 0; i < 8; i++)
#pragma unroll
            for (int j = 0; j < 4; j++) acc[i][j] = 0.f;

#pragma unroll 4
        for (int ks = 0; ks < 16; ks++) {
            uint32_t a[4];
            ldsm_x4(a[0], a[1], a[2], a[3], a_base + ks * 32);
#pragma unroll
            for (int nf2 = 0; nf2 < 4; nf2++) {
                uint32_t b0, b1, b2, b3;
                ldsm_x4(b0, b1, b2, b3, b_base + nf2 * 16 * SA_K * 2 + ks * 32);
                mma16816(acc[nf2 * 2 + 0], a, b0, b2);
                mma16816(acc[nf2 * 2 + 1], a, b1, b3);
            }
        }

        // ---- epilogue: bias + (optional) cross-warp-pair L2 norm ----
        const int tg = lane & 3;
        const int rr = lane >> 2;
        const int row_a = warp_m * 16 + rr;
        const int row_b = row_a + 8;

        float ss_a = 0.f, ss_b = 0.f;
#pragma unroll
        for (int nf = 0; nf < 8; nf++) {
            int n0 = warp_n * 64 + nf * 8 + tg * 2;
            acc[nf][0] += sbias[n0]; acc[nf][1] += sbias[n0 + 1];
            acc[nf][2] += sbias[n0]; acc[nf][3] += sbias[n0 + 1];
            ss_a += acc[nf][0] * acc[nf][0] + acc[nf][1] * acc[nf][1];
            ss_b += acc[nf][2] * acc[nf][2] + acc[nf][3] * acc[nf][3];
        }
        ss_a += __shfl_xor_sync(0xffffffffu, ss_a, 1);
        ss_a += __shfl_xor_sync(0xffffffffu, ss_a, 2);
        ss_b += __shfl_xor_sync(0xffffffffu, ss_b, 1);
        ss_b += __shfl_xor_sync(0xffffffffu, ss_b, 2);

        float scale_a = 1.f, scale_b = 1.f;
        if (do_norm) {
            if (tg == 0) {
                snorm[row_a * 2 + warp_n] = ss_a;
                snorm[row_b * 2 + warp_n] = ss_b;
            }
            __syncthreads();
            float fa = snorm[row_a * 2 + 0] + snorm[row_a * 2 + 1];
            float fb = snorm[row_b * 2 + 0] + snorm[row_b * 2 + 1];
            scale_a = 1.0f / fmaxf(sqrtf(fa), 1e-12f);
            scale_b = 1.0f / fmaxf(sqrtf(fb), 1e-12f);
        } else {
            __syncthreads();   // mma-complete barrier before next tile's staging
        }

        int grow_a = row0 + row_a;
        int grow_b = row0 + row_b;
#pragma unroll
        for (int nf = 0; nf < 8; nf++) {
            int n0 = warp_n * 64 + nf * 8 + tg * 2;
            if (grow_a < N_NODES) {
                float v0 = acc[nf][0] * scale_a, v1 = acc[nf][1] * scale_a;
                if (out) *(float2*)(out + (size_t)grow_a * D + n0) = make_float2(v0, v1);
                if (out16) *(__half2*)(out16 + (size_t)grow_a * D + n0) = __floats2half2_rn(v0, v1);
            }
            if (grow_b < N_NODES) {
                float v0 = acc[nf][2] * scale_b, v1 = acc[nf][3] * scale_b;
                if (out) *(float2*)(out + (size_t)grow_b * D + n0) = make_float2(v0, v1);
                if (out16) *(__half2*)(out16 + (size_t)grow_b * D + n0) = __floats2half2_rn(v0, v1);
            }
        }
        __syncthreads();   // writes done before sA restaged
    }
}

// ---------------- launch ----------------
extern "C" void kernel_launch(void* const* d_in, const int* in_sizes, int n_in,
                              void* d_out, int out_size) {
    const float* x   = (const float*)d_in[0];
    const int* src   = (const int*)d_in[1];
    const int* dst   = (const int*)d_in[2];
    const float* Ws1 = (const float*)d_in[3];
    const float* Wn1 = (const float*)d_in[4];
    const float* b1  = (const float*)d_in[5];
    const float* Ws2 = (const float*)d_in[6];
    const float* Wn2 = (const float*)d_in[7];
    const float* b2  = (const float*)d_in[8];
    float* out = (float*)d_out;

    __half* agg16; cudaGetSymbolAddress((void**)&agg16, g_agg16);
    __half* f16;   cudaGetSymbolAddress((void**)&f16, g_f16);
    int* degi;     cudaGetSymbolAddress((void**)&degi, g_degi);
    int* rowst;    cudaGetSymbolAddress((void**)&rowst, g_rowstart);
    int* cursor;   cudaGetSymbolAddress((void**)&cursor, g_cursor);
    int* col;      cudaGetSymbolAddress((void**)&col, g_col);

    int sms = 148;
    cudaDeviceGetAttribute(&sms, cudaDevAttrMultiProcessorCount, 0);
    cudaFuncSetAttribute(sage_mma_kernel,
                         cudaFuncAttributeMaxDynamicSharedMemorySize, SMEM_MMA);

    const int GATHER_BLOCKS = (N_NODES * 32 + 127) / 128;   // 4 warps/block
    const int CVT_ITEMS = N_NODES * D / 4;

    cudaMemsetAsync(degi, 0, N_NODES * sizeof(int));

    // #1: degree histogram + x -> fp16
    degx2h_kernel<<<(CVT_ITEMS + 255) / 256, 256>>>(dst, degi, x, f16);
    // #2: exclusive scan
    scan_kernel<<<1, 1024>>>(degi, rowst, cursor);
    // #3: CSR fill
    fill_kernel<<<(N_EDGES + 255) / 256, 256>>>(src, dst, cursor, col);
    // #4: layer-1 gather (ncu capture control)
    gather16_kernel<<<GATHER_BLOCKS, 128>>>(f16, rowst, degi, col, agg16);
    // #5: layer-1 tensor GEMM -> fp16 shadow only
    sage_mma_kernel<<<2 * sms, MMA_THREADS, SMEM_MMA>>>(
        f16, agg16, Ws1, Wn1, b1, (float*)0, f16, 0);
    // #6: layer-2 gather
    gather16_kernel<<<GATHER_BLOCKS, 128>>>(f16, rowst, degi, col, agg16);
    // #7: layer-2 tensor GEMM -> fp32 out with L2 norm
    sage_mma_kernel<<<2 * sms, MMA_THREADS, SMEM_MMA>>>(
        f16, agg16, Ws2, Wn2, b2, out, (__half*)0, 1);
}